// round 16
// baseline (speedup 1.0000x reference)
#include <cuda_runtime.h>
#include <cuda_fp16.h>
#include <cstdint>

#define NB 4
#define LL 4096
#define HH 16
#define DD 64
#define MM 64
#define CC 128
#define GG 32
#define NTILE (NB*GG*HH)   // 2048
#define EPS 1e-6f

// half strides
#define HQ 72    // sq, sk, skvpT (64 cols + pad)
#define HT 136   // kT, vT, svT, sS (128 cols + pad); 272B rows -> conflict-free frag reads

__device__ float g_kv [NTILE*DD*MM];
__device__ float g_kvp[NTILE*DD*MM];
__device__ float g_ks [NTILE*DD];
__device__ float g_ksp[NTILE*DD];

__device__ __forceinline__ float phi(float x) { return x > 0.f ? x + 1.f : __expf(x); }
__device__ __forceinline__ uint32_t pack2(float a, float b) {
    __half2 h = __floats2half2_rn(a, b);
    return *(uint32_t*)&h;
}
// fp16 mma: D(f32) = A(f16,16x16,row) * B(f16,16x8,col) + D
__device__ __forceinline__ void mma16(float c[4], uint32_t a0, uint32_t a1, uint32_t a2, uint32_t a3,
                                      uint32_t b0, uint32_t b1) {
    asm volatile("mma.sync.aligned.m16n8k16.row.col.f32.f16.f16.f32 "
                 "{%0,%1,%2,%3},{%4,%5,%6,%7},{%8,%9},{%0,%1,%2,%3};"
                 : "+f"(c[0]), "+f"(c[1]), "+f"(c[2]), "+f"(c[3])
                 : "r"(a0), "r"(a1), "r"(a2), "r"(a3), "r"(b0), "r"(b1));
}
__device__ __forceinline__ uint32_t ld32(const __half* p) { return *(const uint32_t*)p; }

// ---------------------------------------------------------------------------
// k_state: kv[d][m] = sum_c phi(k)[c][d] * v[c][m]  (M=64,N=64,K=128) fp16 mma.
// kT[d][c], vT[m][c] transposed fp16 tiles. 256 threads, 3 CTAs/SM.
// ---------------------------------------------------------------------------
#define S1_KT  0
#define S1_VT  (64*HT)
#define S1_RED (2*64*HT)                    // half offset of f32 sred
#define SMEM1  (S1_RED*2 + 256*4)           // 34816 + 1024 bytes

__global__ __launch_bounds__(256, 3)
void k_state(const float* __restrict__ K, const float* __restrict__ V) {
    extern __shared__ __half smh[];
    __half* kT = smh + S1_KT;
    __half* vT = smh + S1_VT;
    float* sred = (float*)(smh + S1_RED);
    const int tid = threadIdx.x, wid = tid >> 5, lane = tid & 31;
    const int gid = lane >> 2, tg = lane & 3;
    const int b = blockIdx.x, h = b & 15, g = (b >> 4) & 31, n = b >> 9;

    // load + transpose: kT[d][c] = phi(k[c][d]); vT[m][c] = v[c][m]
    #pragma unroll
    for (int it = 0; it < 8; it++) {
        int idx = tid + it * 256;
        int c = idx >> 4, e0 = (idx & 15) * 4;
        int gb = ((n * LL + g * CC + c) * HH + h) * DD + e0;
        float4 k4 = *(const float4*)(K + gb);
        float4 v4 = *(const float4*)(V + gb);
        kT[(e0 + 0) * HT + c] = __float2half_rn(phi(k4.x));
        kT[(e0 + 1) * HT + c] = __float2half_rn(phi(k4.y));
        kT[(e0 + 2) * HT + c] = __float2half_rn(phi(k4.z));
        kT[(e0 + 3) * HT + c] = __float2half_rn(phi(k4.w));
        vT[(e0 + 0) * HT + c] = __float2half_rn(v4.x);
        vT[(e0 + 1) * HT + c] = __float2half_rn(v4.y);
        vT[(e0 + 2) * HT + c] = __float2half_rn(v4.z);
        vT[(e0 + 3) * HT + c] = __float2half_rn(v4.w);
    }
    __syncthreads();

    // ksum partials (row-contiguous now)
    {
        int d = tid & 63, part = tid >> 6;
        float s = 0.f;
        #pragma unroll 8
        for (int c = part * 32; c < part * 32 + 32; c++) s += __half2float(kT[d * HT + c]);
        sred[part * 64 + d] = s;
    }

    // GEMM: warp tile 16(d) x 32(m), K=128 -> 8 k16-steps
    const int d0 = (wid >> 1) * 16, oc = (wid & 1) * 32;
    float cD[4][4];
    #pragma unroll
    for (int nj = 0; nj < 4; nj++)
        #pragma unroll
        for (int q = 0; q < 4; q++) cD[nj][q] = 0.f;

    #pragma unroll
    for (int kk = 0; kk < 8; kk++) {
        int kb = kk * 16 + 2 * tg;
        uint32_t a0 = ld32(&kT[(d0 + gid) * HT + kb]);
        uint32_t a1 = ld32(&kT[(d0 + 8 + gid) * HT + kb]);
        uint32_t a2 = ld32(&kT[(d0 + gid) * HT + kb + 8]);
        uint32_t a3 = ld32(&kT[(d0 + 8 + gid) * HT + kb + 8]);
        #pragma unroll
        for (int nj = 0; nj < 4; nj++) {
            uint32_t b0 = ld32(&vT[(oc + nj * 8 + gid) * HT + kb]);
            uint32_t b1 = ld32(&vT[(oc + nj * 8 + gid) * HT + kb + 8]);
            mma16(cD[nj], a0, a1, a2, a3, b0, b1);
        }
    }

    float* dst = g_kv + (size_t)b * (DD * MM);
    #pragma unroll
    for (int nj = 0; nj < 4; nj++) {
        int col = oc + nj * 8 + 2 * tg;
        *(float2*)(dst + (d0 + gid) * MM + col)     = make_float2(cD[nj][0], cD[nj][1]);
        *(float2*)(dst + (d0 + 8 + gid) * MM + col) = make_float2(cD[nj][2], cD[nj][3]);
    }

    __syncthreads();
    if (tid < 64)
        g_ks[(size_t)b * DD + tid] = sred[tid] + sred[64 + tid] + sred[128 + tid] + sred[192 + tid];
}

// ---------------------------------------------------------------------------
// k_scan: exact R11 version. grid (64,4)x256.
// ---------------------------------------------------------------------------
__global__ __launch_bounds__(256, 4)
void k_scan() {
    const int nh = blockIdx.x, n = nh >> 4, h = nh & 15;
    const int pos = blockIdx.y * 1024 + threadIdx.x * 4;
    float4 acc = make_float4(0.f, 0.f, 0.f, 0.f);
    size_t base0 = ((size_t)(n * GG * HH + h)) * (DD * MM) + pos;
    float4 nxt = *(const float4*)&g_kv[base0];
    for (int g = 0; g < GG; g++) {
        float4 cur = nxt;
        size_t base = ((size_t)((n * GG + g) * HH + h)) * (DD * MM) + pos;
        if (g + 1 < GG) {
            size_t basen = ((size_t)((n * GG + g + 1) * HH + h)) * (DD * MM) + pos;
            nxt = *(const float4*)&g_kv[basen];
        }
        *(float4*)&g_kvp[base] = acc;
        acc.x += cur.x; acc.y += cur.y; acc.z += cur.z; acc.w += cur.w;
    }
    if (blockIdx.y == 0 && threadIdx.x < DD) {
        float a = 0.f;
        for (int g = 0; g < GG; g++) {
            size_t off = (size_t)((n * GG + g) * HH + h) * DD + threadIdx.x;
            g_ksp[off] = a;
            a += g_ks[off];
        }
    }
}

// ---------------------------------------------------------------------------
// k_main: R11 causal-trimmed structure, fp16 fragments. 512 threads, 1 CTA/SM.
// ---------------------------------------------------------------------------
// half-region offsets (in halves)
#define M_SQ    0
#define M_SK    (CC*HQ)                   // 9216
#define M_SVT   (M_SK + CC*HQ)            // 18432
#define M_SS    (M_SVT + 64*HT)           // 27136
#define M_KVPT  (M_SS + CC*HT)            // 44544
#define M_HEND  (M_KVPT + 64*HQ)          // 49152 halves
// f32 region after halves
#define SMEM3   (M_HEND*2 + (64 + 4*CC + CC) * 4)

__global__ __launch_bounds__(512, 1)
void k_main(const float* __restrict__ Q, const float* __restrict__ K,
            const float* __restrict__ V, float* __restrict__ O) {
    extern __shared__ __half smh[];
    __half* sq    = smh + M_SQ;    // [128][HQ]  phi(q)
    __half* sk    = smh + M_SK;    // [128][HQ]  phi(k)
    __half* svT   = smh + M_SVT;   // [64][HT]   v^T  (row m, col c)
    __half* sS    = smh + M_SS;    // [128][HT]  masked S
    __half* skvpT = smh + M_KVPT;  // [64][HQ]   kvp^T (row m, col d)
    float* sksp = (float*)(smh + M_HEND);
    float* szp  = sksp + 64;       // [4][CC]
    float* sz   = szp + 4 * CC;

    const int tid = threadIdx.x, wid = tid >> 5, lane = tid & 31;
    const int gid = lane >> 2, tg = lane & 3;
    const int b = blockIdx.x, h = b & 15, g = (b >> 4) & 31, n = b >> 9;

    // ---- loads ----
    #pragma unroll
    for (int it = 0; it < 4; it++) {
        int idx = tid + it * 512;
        int r = idx >> 4, c0 = (idx & 15) * 4;
        int gb = ((n * LL + g * CC + r) * HH + h) * DD + c0;
        float4 q4 = *(const float4*)(Q + gb);
        float4 k4 = *(const float4*)(K + gb);
        float4 v4 = *(const float4*)(V + gb);
        *(uint32_t*)&sq[r * HQ + c0]     = pack2(phi(q4.x), phi(q4.y));
        *(uint32_t*)&sq[r * HQ + c0 + 2] = pack2(phi(q4.z), phi(q4.w));
        *(uint32_t*)&sk[r * HQ + c0]     = pack2(phi(k4.x), phi(k4.y));
        *(uint32_t*)&sk[r * HQ + c0 + 2] = pack2(phi(k4.z), phi(k4.w));
        // v transpose: svT[m][c]
        svT[(c0 + 0) * HT + r] = __float2half_rn(v4.x);
        svT[(c0 + 1) * HT + r] = __float2half_rn(v4.y);
        svT[(c0 + 2) * HT + r] = __float2half_rn(v4.z);
        svT[(c0 + 3) * HT + r] = __float2half_rn(v4.w);
    }
    {
        const float* src = g_kvp + (size_t)b * (DD * MM);
        #pragma unroll
        for (int it = 0; it < 2; it++) {
            int idx = tid + it * 512;
            int d = idx >> 4, m0 = (idx & 15) * 4;
            float4 s4 = *(const float4*)(src + d * MM + m0);
            skvpT[(m0 + 0) * HQ + d] = __float2half_rn(s4.x);
            skvpT[(m0 + 1) * HQ + d] = __float2half_rn(s4.y);
            skvpT[(m0 + 2) * HQ + d] = __float2half_rn(s4.z);
            skvpT[(m0 + 3) * HQ + d] = __float2half_rn(s4.w);
        }
        if (tid < DD) sksp[tid] = g_ksp[(size_t)b * DD + tid];
    }
    __syncthreads();   // (A)

    const int widq = wid - 8;
    const int gra = widq >> 1, grb = 7 - gra;
    const int ra = gra * 16, rb = grb * 16;
    const int oc = (widq & 1) * 32;
    float cA[4][4], cB[4][4];

    if (wid < 4) {
        // ---- diagonal 32x32 S block ----
        const int r0 = wid * 32, c0g = wid * 32;
        float cS[2][4][4];
        #pragma unroll
        for (int mi = 0; mi < 2; mi++)
            #pragma unroll
            for (int nj = 0; nj < 4; nj++)
                #pragma unroll
                for (int q = 0; q < 4; q++) cS[mi][nj][q] = 0.f;

        #pragma unroll
        for (int kk = 0; kk < 4; kk++) {
            int kb = kk * 16 + 2 * tg;
            uint32_t a[2][4];
            #pragma unroll
            for (int mi = 0; mi < 2; mi++) {
                int ar = r0 + mi * 16;
                a[mi][0] = ld32(&sq[(ar + gid) * HQ + kb]);
                a[mi][1] = ld32(&sq[(ar + 8 + gid) * HQ + kb]);
                a[mi][2] = ld32(&sq[(ar + gid) * HQ + kb + 8]);
                a[mi][3] = ld32(&sq[(ar + 8 + gid) * HQ + kb + 8]);
            }
            #pragma unroll
            for (int nj = 0; nj < 4; nj++) {
                uint32_t b0 = ld32(&sk[(c0g + nj * 8 + gid) * HQ + kb]);
                uint32_t b1 = ld32(&sk[(c0g + nj * 8 + gid) * HQ + kb + 8]);
                mma16(cS[0][nj], a[0][0], a[0][1], a[0][2], a[0][3], b0, b1);
                mma16(cS[1][nj], a[1][0], a[1][1], a[1][2], a[1][3], b0, b1);
            }
        }
        #pragma unroll
        for (int mi = 0; mi < 2; mi++) {
            int rlo = r0 + mi * 16 + gid, rhi = rlo + 8;
            float zlo = 0.f, zhi = 0.f;
            #pragma unroll
            for (int nj = 0; nj < 4; nj++) {
                int c0 = c0g + nj * 8 + 2 * tg, c1 = c0 + 1;
                float s0 = (c0 <= rlo) ? cS[mi][nj][0] : 0.f;
                float s1 = (c1 <= rlo) ? cS[mi][nj][1] : 0.f;
                float s2 = (c0 <= rhi) ? cS[mi][nj][2] : 0.f;
                float s3 = (c1 <= rhi) ? cS[mi][nj][3] : 0.f;
                zlo += s0 + s1;
                zhi += s2 + s3;
                *(uint32_t*)&sS[rlo * HT + c0] = pack2(s0, s1);
                *(uint32_t*)&sS[rhi * HT + c0] = pack2(s2, s3);
            }
            zlo += __shfl_xor_sync(0xffffffffu, zlo, 1);
            zlo += __shfl_xor_sync(0xffffffffu, zlo, 2);
            zhi += __shfl_xor_sync(0xffffffffu, zhi, 1);
            zhi += __shfl_xor_sync(0xffffffffu, zhi, 2);
            if (tg == 0) {
                szp[wid * CC + rlo] = zlo;
                szp[wid * CC + rhi] = zhi;
            }
        }
    } else if (wid < 8) {
        // ---- three below-diagonal 16x32 S blocks ----
        const int w = wid - 4;
        const int GRt[4][3] = {{2,4,6},{3,5,7},{4,5,6},{7,6,7}};
        const int CGt[4][3] = {{0,0,0},{0,0,0},{1,1,1},{1,2,2}};
        #pragma unroll
        for (int t = 0; t < 3; t++) {
            const int gr = GRt[w][t], cg = CGt[w][t];
            const int r0 = gr * 16, c0g = cg * 32;
            float cT[4][4];
            #pragma unroll
            for (int nj = 0; nj < 4; nj++)
                #pragma unroll
                for (int q = 0; q < 4; q++) cT[nj][q] = 0.f;

            #pragma unroll
            for (int kk = 0; kk < 4; kk++) {
                int kb = kk * 16 + 2 * tg;
                uint32_t a0 = ld32(&sq[(r0 + gid) * HQ + kb]);
                uint32_t a1 = ld32(&sq[(r0 + 8 + gid) * HQ + kb]);
                uint32_t a2 = ld32(&sq[(r0 + gid) * HQ + kb + 8]);
                uint32_t a3 = ld32(&sq[(r0 + 8 + gid) * HQ + kb + 8]);
                #pragma unroll
                for (int nj = 0; nj < 4; nj++) {
                    uint32_t b0 = ld32(&sk[(c0g + nj * 8 + gid) * HQ + kb]);
                    uint32_t b1 = ld32(&sk[(c0g + nj * 8 + gid) * HQ + kb + 8]);
                    mma16(cT[nj], a0, a1, a2, a3, b0, b1);
                }
            }
            int rlo = r0 + gid, rhi = rlo + 8;
            float zlo = 0.f, zhi = 0.f;
            #pragma unroll
            for (int nj = 0; nj < 4; nj++) {
                int c0 = c0g + nj * 8 + 2 * tg;
                zlo += cT[nj][0] + cT[nj][1];
                zhi += cT[nj][2] + cT[nj][3];
                *(uint32_t*)&sS[rlo * HT + c0] = pack2(cT[nj][0], cT[nj][1]);
                *(uint32_t*)&sS[rhi * HT + c0] = pack2(cT[nj][2], cT[nj][3]);
            }
            zlo += __shfl_xor_sync(0xffffffffu, zlo, 1);
            zlo += __shfl_xor_sync(0xffffffffu, zlo, 2);
            zhi += __shfl_xor_sync(0xffffffffu, zhi, 1);
            zhi += __shfl_xor_sync(0xffffffffu, zhi, 2);
            if (tg == 0) {
                szp[cg * CC + rlo] = zlo;
                szp[cg * CC + rhi] = zhi;
            }
        }
    } else {
        // ---- O_inter = phi(q) @ kvp : rows ra, rb x 32 cols, K=64 (4 steps) ----
        #pragma unroll
        for (int nj = 0; nj < 4; nj++)
            #pragma unroll
            for (int q = 0; q < 4; q++) { cA[nj][q] = 0.f; cB[nj][q] = 0.f; }

        #pragma unroll
        for (int kk = 0; kk < 4; kk++) {
            int kb = kk * 16 + 2 * tg;
            uint32_t aA0 = ld32(&sq[(ra + gid) * HQ + kb]);
            uint32_t aA1 = ld32(&sq[(ra + 8 + gid) * HQ + kb]);
            uint32_t aA2 = ld32(&sq[(ra + gid) * HQ + kb + 8]);
            uint32_t aA3 = ld32(&sq[(ra + 8 + gid) * HQ + kb + 8]);
            uint32_t aB0 = ld32(&sq[(rb + gid) * HQ + kb]);
            uint32_t aB1 = ld32(&sq[(rb + 8 + gid) * HQ + kb]);
            uint32_t aB2 = ld32(&sq[(rb + gid) * HQ + kb + 8]);
            uint32_t aB3 = ld32(&sq[(rb + 8 + gid) * HQ + kb + 8]);
            #pragma unroll
            for (int nj = 0; nj < 4; nj++) {
                uint32_t b0 = ld32(&skvpT[(oc + nj * 8 + gid) * HQ + kb]);
                uint32_t b1 = ld32(&skvpT[(oc + nj * 8 + gid) * HQ + kb + 8]);
                mma16(cA[nj], aA0, aA1, aA2, aA3, b0, b1);
                mma16(cB[nj], aB0, aB1, aB2, aB3, b0, b1);
            }
        }
    }
    __syncthreads();   // (B)

    if (wid < 8) {
        // ---- z ----
        if (tid < CC) {
            int r = tid, rg = r >> 5;
            float qd = EPS;
            #pragma unroll 8
            for (int d = 0; d < DD; d++) qd += __half2float(sq[r * HQ + d]) * sksp[d];
            float s = szp[r];
            if (rg >= 1) s += szp[CC + r];
            if (rg >= 2) s += szp[2 * CC + r];
            if (rg >= 3) s += szp[3 * CC + r];
            sz[r] = qd + s;
        }
    } else {
        // ---- O_intra: k16-steps trimmed to gr+1 per row tile ----
        const int nka = gra + 1, nkb = grb + 1;
        for (int kk = 0; kk < nka; kk++) {
            int kb = kk * 16 + 2 * tg;
            uint32_t a0 = ld32(&sS[(ra + gid) * HT + kb]);
            uint32_t a1 = ld32(&sS[(ra + 8 + gid) * HT + kb]);
            uint32_t a2 = ld32(&sS[(ra + gid) * HT + kb + 8]);
            uint32_t a3 = ld32(&sS[(ra + 8 + gid) * HT + kb + 8]);
            #pragma unroll
            for (int nj = 0; nj < 4; nj++) {
                uint32_t b0 = ld32(&svT[(oc + nj * 8 + gid) * HT + kb]);
                uint32_t b1 = ld32(&svT[(oc + nj * 8 + gid) * HT + kb + 8]);
                mma16(cA[nj], a0, a1, a2, a3, b0, b1);
            }
        }
        for (int kk = 0; kk < nkb; kk++) {
            int kb = kk * 16 + 2 * tg;
            uint32_t a0 = ld32(&sS[(rb + gid) * HT + kb]);
            uint32_t a1 = ld32(&sS[(rb + 8 + gid) * HT + kb]);
            uint32_t a2 = ld32(&sS[(rb + gid) * HT + kb + 8]);
            uint32_t a3 = ld32(&sS[(rb + 8 + gid) * HT + kb + 8]);
            #pragma unroll
            for (int nj = 0; nj < 4; nj++) {
                uint32_t b0 = ld32(&svT[(oc + nj * 8 + gid) * HT + kb]);
                uint32_t b1 = ld32(&svT[(oc + nj * 8 + gid) * HT + kb + 8]);
                mma16(cB[nj], a0, a1, a2, a3, b0, b1);
            }
        }
    }
    __syncthreads();   // (C)

    if (wid >= 8) {
        int rlo = ra + gid, rhi = rlo + 8;
        float izlo = 1.f / sz[rlo], izhi = 1.f / sz[rhi];
        float* oblo = O + ((size_t)((n * LL + g * CC + rlo) * HH + h)) * MM;
        float* obhi = O + ((size_t)((n * LL + g * CC + rhi) * HH + h)) * MM;
        #pragma unroll
        for (int nj = 0; nj < 4; nj++) {
            int c0 = oc + nj * 8 + 2 * tg;
            *(float2*)(oblo + c0) = make_float2(cA[nj][0] * izlo, cA[nj][1] * izlo);
            *(float2*)(obhi + c0) = make_float2(cA[nj][2] * izhi, cA[nj][3] * izhi);
        }
        rlo = rb + gid; rhi = rlo + 8;
        izlo = 1.f / sz[rlo]; izhi = 1.f / sz[rhi];
        oblo = O + ((size_t)((n * LL + g * CC + rlo) * HH + h)) * MM;
        obhi = O + ((size_t)((n * LL + g * CC + rhi) * HH + h)) * MM;
        #pragma unroll
        for (int nj = 0; nj < 4; nj++) {
            int c0 = oc + nj * 8 + 2 * tg;
            *(float2*)(oblo + c0) = make_float2(cB[nj][0] * izlo, cB[nj][1] * izlo);
            *(float2*)(obhi + c0) = make_float2(cB[nj][2] * izhi, cB[nj][3] * izhi);
        }
    }
}

// ---------------------------------------------------------------------------
extern "C" void kernel_launch(void* const* d_in, const int* in_sizes, int n_in,
                              void* d_out, int out_size) {
    const float* Q = (const float*)d_in[0];
    const float* K = (const float*)d_in[1];
    const float* V = (const float*)d_in[2];
    float* O = (float*)d_out;

    cudaFuncSetAttribute(k_state, cudaFuncAttributeMaxDynamicSharedMemorySize, SMEM1);
    cudaFuncSetAttribute(k_main,  cudaFuncAttributeMaxDynamicSharedMemorySize, SMEM3);

    k_state<<<NTILE, 256, SMEM1>>>(K, V);
    k_scan<<<dim3(NB * HH, 4), 256>>>();
    k_main<<<NTILE, 512, SMEM3>>>(Q, K, V, O);
}